// round 9
// baseline (speedup 1.0000x reference)
#include <cuda_runtime.h>

#define NB 16
#define NC 3
#define IH 720
#define IW 1280
#define OUT 255
#define PER_B (NC*IH*IW)          /* 2764800 floats per batch image */
#define PER_B4 (PER_B/4)          /* 691200 float4 per batch image */
#define RBLK 74                   /* reduce slices per batch */
#define NBLK (RBLK*NB)            /* 1184 blocks */
#define RTHREADS 128              /* reduce-role threads per block */
#define RSTRIDE (RBLK*RTHREADS)   /* 9472 float4 */
#define NTILE (NB*OUT)            /* 4080 output rows */

__device__ float d_partial[NB * RBLK];
__device__ float d_mean[NB];
__device__ unsigned int d_count = 0;   /* wrapping counter -> graph-replay safe */
__device__ volatile int d_flag = 0;    /* means-ready release flag */

// ---------------------------------------------------------------------------
// Bilinear helpers. pixel_main stores the valid-corner blend and reports
// whether the pixel has any OOB corner; pixel_patch recomputes w_inv and adds
// the mean contribution (same fp expressions -> identical values).
// ---------------------------------------------------------------------------
__device__ __forceinline__ void pixel_coords(int b, int oy, int ox,
                                             const float* __restrict__ pos,
                                             const float* __restrict__ szs,
                                             int& o00, int& o01, int& o10, int& o11,
                                             bool& v00, bool& v01, bool& v10, bool& v11,
                                             float& wx, float& wy) {
    const float sz    = __ldg(&szs[b]);
    const float half  = (sz + 1.0f) * 0.5f;
    const float xmin  = rintf(__ldg(&pos[2 * b + 0]) - half);   /* jnp.round */
    const float ymin  = rintf(__ldg(&pos[2 * b + 1]) - half);
    const float scale = sz / (float)OUT;
    const float szm1  = sz - 1.0f;

    float sx = fminf(fmaxf(((float)ox + 0.5f) * scale - 0.5f, 0.0f), szm1);
    float lx = floorf(sx);
    wx = sx - lx;
    float hx = fminf(lx + 1.0f, szm1);

    float sy = fminf(fmaxf(((float)oy + 0.5f) * scale - 0.5f, 0.0f), szm1);
    float ly = floorf(sy);
    wy = sy - ly;
    float hy = fminf(ly + 1.0f, szm1);

    float y0 = ly + ymin, y1 = hy + ymin;
    float x0 = lx + xmin, x1 = hx + xmin;

    bool vy0 = (y0 >= 0.0f) & (y0 <= (float)(IH - 1));
    bool vy1 = (y1 >= 0.0f) & (y1 <= (float)(IH - 1));
    bool vx0 = (x0 >= 0.0f) & (x0 <= (float)(IW - 1));
    bool vx1 = (x1 >= 0.0f) & (x1 <= (float)(IW - 1));
    int iy0 = (int)fminf(fmaxf(y0, 0.0f), (float)(IH - 1));
    int iy1 = (int)fminf(fmaxf(y1, 0.0f), (float)(IH - 1));
    int ix0 = (int)fminf(fmaxf(x0, 0.0f), (float)(IW - 1));
    int ix1 = (int)fminf(fmaxf(x1, 0.0f), (float)(IW - 1));
    v00 = vy0 & vx0; v01 = vy0 & vx1; v10 = vy1 & vx0; v11 = vy1 & vx1;
    o00 = iy0 * IW + ix0; o01 = iy0 * IW + ix1;
    o10 = iy1 * IW + ix0; o11 = iy1 * IW + ix1;
}

__device__ __forceinline__ bool pixel_main(const float* __restrict__ im,
                                           float* __restrict__ out,
                                           int b, int oy, int ox,
                                           const float* __restrict__ pos,
                                           const float* __restrict__ szs) {
    int o00, o01, o10, o11; bool v00, v01, v10, v11; float wx, wy;
    pixel_coords(b, oy, ox, pos, szs, o00, o01, o10, o11, v00, v01, v10, v11, wx, wy);

    const float omwx = 1.0f - wx, omwy = 1.0f - wy;
    const float* base = im + (size_t)b * PER_B;
    float* orow = out + ((size_t)(b * NC) * OUT + oy) * OUT + ox;

    #pragma unroll
    for (int c = 0; c < NC; c++) {
        const float* pl = base + c * (IH * IW);
        float p00 = v00 ? __ldg(&pl[o00]) : 0.0f;
        float p01 = v01 ? __ldg(&pl[o01]) : 0.0f;
        float p10 = v10 ? __ldg(&pl[o10]) : 0.0f;
        float p11 = v11 ? __ldg(&pl[o11]) : 0.0f;
        orow[c * (OUT * OUT)] =
            (p00 * omwx + p01 * wx) * omwy + (p10 * omwx + p11 * wx) * wy;
    }
    return !(v00 & v01 & v10 & v11);
}

__device__ __forceinline__ void pixel_patch(float* __restrict__ out,
                                            int b, int oy, int ox,
                                            const float* __restrict__ pos,
                                            const float* __restrict__ szs,
                                            float mean) {
    int o00, o01, o10, o11; bool v00, v01, v10, v11; float wx, wy;
    pixel_coords(b, oy, ox, pos, szs, o00, o01, o10, o11, v00, v01, v10, v11, wx, wy);

    const float omwx = 1.0f - wx, omwy = 1.0f - wy;
    const float w00 = omwx * omwy, w01 = wx * omwy;
    const float w10 = omwx * wy,  w11 = wx * wy;
    float w_inv = (v00 ? 0.0f : w00) + (v01 ? 0.0f : w01) +
                  (v10 ? 0.0f : w10) + (v11 ? 0.0f : w11);
    float add = w_inv * mean;
    float* orow = out + ((size_t)(b * NC) * OUT + oy) * OUT + ox;
    #pragma unroll
    for (int c = 0; c < NC; c++) orow[c * (OUT * OUT)] += add;
}

// ---------------------------------------------------------------------------
// Fused kernel. grid (RBLK, NB) = 1184 blocks x 256 threads, 8 blocks/SM.
// Warps 0-3: mean reduction. Warps 4-7: bilinear output rows.
// No cross-role synchronization except the device flag.
// ---------------------------------------------------------------------------
__global__ void __launch_bounds__(256, 8)
fused_kernel(const float* __restrict__ im,
             const float* __restrict__ pos,
             const float* __restrict__ szs,
             float* __restrict__ out) {
    const int bid = blockIdx.y * RBLK + blockIdx.x;   /* 0..1183 */
    const int tid = threadIdx.x;

    __shared__ float sm4[4];

    if (tid < RTHREADS) {
        /* ---------------- reduce role: warps 0-3 ---------------- */
        const int b   = blockIdx.y;
        const int blk = blockIdx.x;
        const float4* __restrict__ p = (const float4*)(im + (size_t)b * PER_B);

        float a0 = 0.f, a1 = 0.f, a2 = 0.f, a3 = 0.f;
        int i = blk * RTHREADS + tid;
        for (; i + 3 * RSTRIDE < PER_B4; i += 4 * RSTRIDE) {
            float4 v0 = p[i];
            float4 v1 = p[i + RSTRIDE];
            float4 v2 = p[i + 2 * RSTRIDE];
            float4 v3 = p[i + 3 * RSTRIDE];
            a0 += (v0.x + v0.y) + (v0.z + v0.w);
            a1 += (v1.x + v1.y) + (v1.z + v1.w);
            a2 += (v2.x + v2.y) + (v2.z + v2.w);
            a3 += (v3.x + v3.y) + (v3.z + v3.w);
        }
        for (; i < PER_B4; i += RSTRIDE) {
            float4 v = p[i];
            a0 += (v.x + v.y) + (v.z + v.w);
        }
        float s = (a0 + a1) + (a2 + a3);

        /* warp sums -> smem -> lane0 of warp0 */
        #pragma unroll
        for (int o = 16; o > 0; o >>= 1) s += __shfl_down_sync(0xffffffffu, s, o);
        const int w = tid >> 5, l = tid & 31;
        if (l == 0) sm4[w] = s;
        asm volatile("bar.sync 1, 128;" ::: "memory");   /* reduce warps only */

        if (w == 0) {
            int last = 0;
            if (l == 0) {
                float bs = (sm4[0] + sm4[1]) + (sm4[2] + sm4[3]);
                d_partial[b * RBLK + blk] = bs;
                __threadfence();
                unsigned int old = atomicInc(&d_count, NBLK - 1);
                last = (old == NBLK - 1);
            }
            last = __shfl_sync(0xffffffffu, last, 0);

            if (last) {
                /* finalize all 16 means with this single warp */
                for (int bb = 0; bb < NB; bb++) {
                    const float* pp = &d_partial[bb * RBLK];
                    float s2 = __ldcg(&pp[l]) + __ldcg(&pp[l + 32]);
                    if (l < RBLK - 64) s2 += __ldcg(&pp[l + 64]);
                    #pragma unroll
                    for (int o = 16; o > 0; o >>= 1)
                        s2 += __shfl_down_sync(0xffffffffu, s2, o);
                    if (l == 0) d_mean[bb] = s2 * (1.0f / (float)PER_B);
                }
                if (l == 0) {
                    __threadfence();
                    atomicExch((int*)&d_flag, 1);
                }
            }
        }
    } else {
        /* ---------------- bilinear role: warps 4-7 ---------------- */
        const int tid2 = tid - RTHREADS;               /* 0..127 */

        unsigned int patch_mask = 0;                   /* bit k*2+p: pixel needs mean */
        int tb[4], toy[4];

        #pragma unroll
        for (int k = 0; k < 4; k++) {
            int tile = bid + k * NBLK;
            if (tile >= NTILE) { tb[k] = -1; continue; }
            int b2 = tile / OUT;
            int oy = tile - b2 * OUT;
            tb[k] = b2; toy[k] = oy;

            if (pixel_main(im, out, b2, oy, tid2, pos, szs))
                patch_mask |= 1u << (k * 2);
            if (tid2 + RTHREADS < OUT) {
                if (pixel_main(im, out, b2, oy, tid2 + RTHREADS, pos, szs))
                    patch_mask |= 1u << (k * 2 + 1);
            }
        }

        if (patch_mask) {
            while (d_flag == 0) __nanosleep(200);      /* reduce warps always progress */
            #pragma unroll
            for (int k = 0; k < 4; k++) {
                if (tb[k] < 0) continue;
                float mean = __ldcg(&d_mean[tb[k]]);
                if (patch_mask & (1u << (k * 2)))
                    pixel_patch(out, tb[k], toy[k], tid2, pos, szs, mean);
                if (patch_mask & (1u << (k * 2 + 1)))
                    pixel_patch(out, tb[k], toy[k], tid2 + RTHREADS, pos, szs, mean);
            }
        }
    }
}

// ---------------------------------------------------------------------------
extern "C" void kernel_launch(void* const* d_in, const int* in_sizes, int n_in,
                              void* d_out, int out_size) {
    const float* im  = (const float*)d_in[0];
    const float* pos = (const float*)d_in[1];
    const float* szs = (const float*)d_in[2];
    float* out = (float*)d_out;

    fused_kernel<<<dim3(RBLK, NB), 256>>>(im, pos, szs, out);
}

// round 10
// speedup vs baseline: 1.0100x; 1.0100x over previous
#include <cuda_runtime.h>

#define NB 16
#define NC 3
#define IH 720
#define IW 1280
#define OUT 255
#define PER_B (NC*IH*IW)          /* 2764800 floats per batch image */
#define PER_B4 (PER_B/4)          /* 691200 float4 per batch image */
#define RBLK 74                   /* reduce slices per batch */
#define NBLK (RBLK*NB)            /* 1184 blocks = 8 per SM exactly */
#define RSTRIDE (RBLK*128)        /* 9472 float4: stride of a 128-thread sweep */
#define NITER 73                  /* ceil(PER_B4 / RSTRIDE) iterations per stream */
#define JSPLIT 43                 /* warps 0-3 do [0,43), warps 4-7 do [43,73) */
#define NTILE (NB*OUT)            /* 4080 output rows */

__device__ float d_partial[NB * RBLK];
__device__ float d_mean[NB];
__device__ unsigned int d_count = 0;   /* wrapping counter -> graph-replay safe */
__device__ volatile int d_flag = 0;    /* means-ready release flag */

// ---------------------------------------------------------------------------
// Bilinear helpers (identical fp expressions in main and patch passes).
// ---------------------------------------------------------------------------
__device__ __forceinline__ void pixel_coords(int b, int oy, int ox,
                                             const float* __restrict__ pos,
                                             const float* __restrict__ szs,
                                             int& o00, int& o01, int& o10, int& o11,
                                             bool& v00, bool& v01, bool& v10, bool& v11,
                                             float& wx, float& wy) {
    const float sz    = __ldg(&szs[b]);
    const float half  = (sz + 1.0f) * 0.5f;
    const float xmin  = rintf(__ldg(&pos[2 * b + 0]) - half);   /* jnp.round */
    const float ymin  = rintf(__ldg(&pos[2 * b + 1]) - half);
    const float scale = sz / (float)OUT;
    const float szm1  = sz - 1.0f;

    float sx = fminf(fmaxf(((float)ox + 0.5f) * scale - 0.5f, 0.0f), szm1);
    float lx = floorf(sx);
    wx = sx - lx;
    float hx = fminf(lx + 1.0f, szm1);

    float sy = fminf(fmaxf(((float)oy + 0.5f) * scale - 0.5f, 0.0f), szm1);
    float ly = floorf(sy);
    wy = sy - ly;
    float hy = fminf(ly + 1.0f, szm1);

    float y0 = ly + ymin, y1 = hy + ymin;
    float x0 = lx + xmin, x1 = hx + xmin;

    bool vy0 = (y0 >= 0.0f) & (y0 <= (float)(IH - 1));
    bool vy1 = (y1 >= 0.0f) & (y1 <= (float)(IH - 1));
    bool vx0 = (x0 >= 0.0f) & (x0 <= (float)(IW - 1));
    bool vx1 = (x1 >= 0.0f) & (x1 <= (float)(IW - 1));
    int iy0 = (int)fminf(fmaxf(y0, 0.0f), (float)(IH - 1));
    int iy1 = (int)fminf(fmaxf(y1, 0.0f), (float)(IH - 1));
    int ix0 = (int)fminf(fmaxf(x0, 0.0f), (float)(IW - 1));
    int ix1 = (int)fminf(fmaxf(x1, 0.0f), (float)(IW - 1));
    v00 = vy0 & vx0; v01 = vy0 & vx1; v10 = vy1 & vx0; v11 = vy1 & vx1;
    o00 = iy0 * IW + ix0; o01 = iy0 * IW + ix1;
    o10 = iy1 * IW + ix0; o11 = iy1 * IW + ix1;
}

__device__ __forceinline__ bool pixel_main(const float* __restrict__ im,
                                           float* __restrict__ out,
                                           int b, int oy, int ox,
                                           const float* __restrict__ pos,
                                           const float* __restrict__ szs) {
    int o00, o01, o10, o11; bool v00, v01, v10, v11; float wx, wy;
    pixel_coords(b, oy, ox, pos, szs, o00, o01, o10, o11, v00, v01, v10, v11, wx, wy);

    const float omwx = 1.0f - wx, omwy = 1.0f - wy;
    const float* base = im + (size_t)b * PER_B;
    float* orow = out + ((size_t)(b * NC) * OUT + oy) * OUT + ox;

    #pragma unroll
    for (int c = 0; c < NC; c++) {
        const float* pl = base + c * (IH * IW);
        float p00 = v00 ? __ldg(&pl[o00]) : 0.0f;
        float p01 = v01 ? __ldg(&pl[o01]) : 0.0f;
        float p10 = v10 ? __ldg(&pl[o10]) : 0.0f;
        float p11 = v11 ? __ldg(&pl[o11]) : 0.0f;
        orow[c * (OUT * OUT)] =
            (p00 * omwx + p01 * wx) * omwy + (p10 * omwx + p11 * wx) * wy;
    }
    return !(v00 & v01 & v10 & v11);
}

__device__ __forceinline__ void pixel_patch(float* __restrict__ out,
                                            int b, int oy, int ox,
                                            const float* __restrict__ pos,
                                            const float* __restrict__ szs,
                                            float mean) {
    int o00, o01, o10, o11; bool v00, v01, v10, v11; float wx, wy;
    pixel_coords(b, oy, ox, pos, szs, o00, o01, o10, o11, v00, v01, v10, v11, wx, wy);

    const float omwx = 1.0f - wx, omwy = 1.0f - wy;
    const float w00 = omwx * omwy, w01 = wx * omwy;
    const float w10 = omwx * wy,  w11 = wx * wy;
    float w_inv = (v00 ? 0.0f : w00) + (v01 ? 0.0f : w01) +
                  (v10 ? 0.0f : w10) + (v11 ? 0.0f : w11);
    float add = w_inv * mean;
    float* orow = out + ((size_t)(b * NC) * OUT + oy) * OUT + ox;
    #pragma unroll
    for (int c = 0; c < NC; c++) orow[c * (OUT * OUT)] += add;
}

// ---------------------------------------------------------------------------
// Fused kernel: late-join work split.
// Warps 0-3: reduce iterations [0, JSPLIT).
// Warps 4-7: bilinear pixels first, then reduce iterations [JSPLIT, NITER).
// Block sum -> partial -> wrapping counter -> last block finalizes + flag.
// Patch (warps 4-7) runs after the block partial is submitted (deadlock-free).
// ---------------------------------------------------------------------------
__global__ void __launch_bounds__(256, 8)
fused_kernel(const float* __restrict__ im,
             const float* __restrict__ pos,
             const float* __restrict__ szs,
             float* __restrict__ out) {
    const int bid = blockIdx.y * RBLK + blockIdx.x;   /* 0..1183 */
    const int tid = threadIdx.x;
    const int b   = blockIdx.y;
    const int blk = blockIdx.x;

    __shared__ float sm8[8];

    const float4* __restrict__ p = (const float4*)(im + (size_t)b * PER_B);
    float s;
    unsigned int patch_mask = 0;

    if (tid < 128) {
        /* ------- reduce front half: iterations [0, JSPLIT), always in bounds ------- */
        const int i0 = blk * 128 + tid;
        float a0 = 0.f, a1 = 0.f, a2 = 0.f, a3 = 0.f;
        int j = 0;
        for (; j + 4 <= JSPLIT; j += 4) {
            int i = i0 + j * RSTRIDE;
            float4 v0 = p[i];
            float4 v1 = p[i + RSTRIDE];
            float4 v2 = p[i + 2 * RSTRIDE];
            float4 v3 = p[i + 3 * RSTRIDE];
            a0 += (v0.x + v0.y) + (v0.z + v0.w);
            a1 += (v1.x + v1.y) + (v1.z + v1.w);
            a2 += (v2.x + v2.y) + (v2.z + v2.w);
            a3 += (v3.x + v3.y) + (v3.z + v3.w);
        }
        for (; j < JSPLIT; j++) {
            float4 v = p[i0 + j * RSTRIDE];
            a0 += (v.x + v.y) + (v.z + v.w);
        }
        s = (a0 + a1) + (a2 + a3);
    } else {
        /* ------- bilinear pixels first ------- */
        const int tid2 = tid - 128;                   /* 0..127 */
        #pragma unroll
        for (int k = 0; k < 4; k++) {
            int tile = bid + k * NBLK;
            if (tile >= NTILE) break;
            int b2 = tile / OUT;
            int oy = tile - b2 * OUT;
            if (pixel_main(im, out, b2, oy, tid2, pos, szs))
                patch_mask |= 1u << (k * 2);
            if (tid2 + 128 < OUT) {
                if (pixel_main(im, out, b2, oy, tid2 + 128, pos, szs))
                    patch_mask |= 1u << (k * 2 + 1);
            }
        }

        /* ------- late-join reduce tail: iterations [JSPLIT, NITER) ------- */
        const int i0 = blk * 128 + tid2;
        float a0 = 0.f, a1 = 0.f, a2 = 0.f, a3 = 0.f;
        int i = i0 + JSPLIT * RSTRIDE;
        for (; i + 3 * RSTRIDE < PER_B4; i += 4 * RSTRIDE) {
            float4 v0 = p[i];
            float4 v1 = p[i + RSTRIDE];
            float4 v2 = p[i + 2 * RSTRIDE];
            float4 v3 = p[i + 3 * RSTRIDE];
            a0 += (v0.x + v0.y) + (v0.z + v0.w);
            a1 += (v1.x + v1.y) + (v1.z + v1.w);
            a2 += (v2.x + v2.y) + (v2.z + v2.w);
            a3 += (v3.x + v3.y) + (v3.z + v3.w);
        }
        for (; i < PER_B4; i += RSTRIDE) {
            float4 v = p[i];
            a0 += (v.x + v.y) + (v.z + v.w);
        }
        s = (a0 + a1) + (a2 + a3);
    }

    /* ------- block-level combine ------- */
    #pragma unroll
    for (int o = 16; o > 0; o >>= 1) s += __shfl_down_sync(0xffffffffu, s, o);
    const int w = tid >> 5, l = tid & 31;
    if (l == 0) sm8[w] = s;
    __syncthreads();

    if (w == 0) {
        int last = 0;
        if (l == 0) {
            float bs = ((sm8[0] + sm8[1]) + (sm8[2] + sm8[3])) +
                       ((sm8[4] + sm8[5]) + (sm8[6] + sm8[7]));
            d_partial[b * RBLK + blk] = bs;
            __threadfence();
            unsigned int old = atomicInc(&d_count, NBLK - 1);
            last = (old == NBLK - 1);
        }
        last = __shfl_sync(0xffffffffu, last, 0);

        if (last) {
            for (int bb = 0; bb < NB; bb++) {
                const float* pp = &d_partial[bb * RBLK];
                float s2 = __ldcg(&pp[l]) + __ldcg(&pp[l + 32]);
                if (l < RBLK - 64) s2 += __ldcg(&pp[l + 64]);
                #pragma unroll
                for (int o = 16; o > 0; o >>= 1)
                    s2 += __shfl_down_sync(0xffffffffu, s2, o);
                if (l == 0) d_mean[bb] = s2 * (1.0f / (float)PER_B);
            }
            if (l == 0) {
                __threadfence();
                atomicExch((int*)&d_flag, 1);
            }
        }
    }

    /* ------- patch (only OOB pixels; partial already submitted -> safe) ------- */
    if (patch_mask) {
        while (d_flag == 0) __nanosleep(200);
        const int tid2 = tid - 128;
        #pragma unroll
        for (int k = 0; k < 4; k++) {
            if (!(patch_mask >> (k * 2) & 3u)) continue;
            int tile = bid + k * NBLK;
            int b2 = tile / OUT;
            int oy = tile - b2 * OUT;
            float mean = __ldcg(&d_mean[b2]);
            if (patch_mask & (1u << (k * 2)))
                pixel_patch(out, b2, oy, tid2, pos, szs, mean);
            if (patch_mask & (1u << (k * 2 + 1)))
                pixel_patch(out, b2, oy, tid2 + 128, pos, szs, mean);
        }
    }
}

// ---------------------------------------------------------------------------
extern "C" void kernel_launch(void* const* d_in, const int* in_sizes, int n_in,
                              void* d_out, int out_size) {
    const float* im  = (const float*)d_in[0];
    const float* pos = (const float*)d_in[1];
    const float* szs = (const float*)d_in[2];
    float* out = (float*)d_out;

    fused_kernel<<<dim3(RBLK, NB), 256>>>(im, pos, szs, out);
}